// round 1
// baseline (speedup 1.0000x reference)
#include <cuda_runtime.h>
#include <math_constants.h>

// Problem constants
namespace {
constexpr int B_ = 2, S_ = 4096, D_ = 512, H_ = 8, DH = 64;
constexpr int MR = B_ * S_;                       // 8192 rows of x
constexpr long long SA_ELEMS = (long long)MR * D_; // 4194304
}

// Scratch (allocation-free rule: __device__ globals)
__device__ float g_q[MR * D_];     // q in [b, s, h*64+d] row-major (ld=512)
__device__ float g_k[MR * D_];
__device__ float g_v[MR * D_];
__device__ float g_ctx[MR * D_];   // attn@V in [b, s, h*64+v]
__device__ float g_m[H_ * B_ * S_];  // per-row softmax max
__device__ float g_l[H_ * B_ * S_];  // per-row softmax denom

// ---------------------------------------------------------------------------
// Generic register-tiled fp32 GEMM.
// MODE 0: C = A@B + bias                (projections)
// MODE 1: C = (A@B^T) * alpha           (scores; batched over z = h*B+b,
//            A = Q head slice, B = K head slice, C = raw[z])
// MODE 2: C = softmax(A_raw)@B          (PV; batched; A-tile loader applies
//            causal mask + exp((x-m)/l); k-loop bounded by causal limit)
// ---------------------------------------------------------------------------
template<int MODE, int BM, int BN, int BK, int TM, int TN>
__global__ __launch_bounds__((BM/TM)*(BN/TN))
void gemm_kernel(const float* __restrict__ A, int lda,
                 const float* __restrict__ Bm, int ldb,
                 const float* __restrict__ bias,
                 float* __restrict__ C, int ldc,
                 int M, int N, int K, float alpha,
                 const float* __restrict__ rowm,
                 const float* __restrict__ rowl)
{
    constexpr int NT = (BM / TM) * (BN / TN);   // 256 threads
    constexpr int STATN = (MODE == 2) ? BM : 1;

    __shared__ float As[BK][BM];
    __shared__ float Bs[BK][BN];
    __shared__ float sm_m[STATN];
    __shared__ float sm_il[STATN];

    const int tid = threadIdx.x;
    const int bx  = blockIdx.x;
    int by = blockIdx.y;
    if (MODE == 2) by = gridDim.y - 1 - by;    // heaviest causal tiles first
    const int z = blockIdx.z;

    size_t aoff = 0, boff = 0, coff = 0;
    int statoff = 0;
    if (MODE == 1) {
        const int h = z >> 1, b = z & 1;
        aoff = (size_t)b * S_ * D_ + (size_t)h * DH;
        boff = aoff;
        coff = (size_t)z * S_ * S_;
    } else if (MODE == 2) {
        const int h = z >> 1, b = z & 1;
        aoff = (size_t)z * S_ * S_;
        boff = (size_t)b * S_ * D_ + (size_t)h * DH;
        coff = boff;
        statoff = z * S_;
    }

    if (MODE == 2) {
        if (tid < BM) {
            sm_m[tid]  = rowm[statoff + by * BM + tid];
            sm_il[tid] = 1.0f / rowl[statoff + by * BM + tid];
        }
    }

    int kend = K;
    if (MODE == 2) kend = min(K, by * BM + BM);   // causal: j <= i_max

    constexpr int TCOLS = BN / TN;
    const int trow = tid / TCOLS;
    const int tcol = tid % TCOLS;

    float acc[TM][TN];
    #pragma unroll
    for (int m = 0; m < TM; m++)
        #pragma unroll
        for (int n = 0; n < TN; n++) acc[m][n] = 0.f;

    // A-tile loader mapping (float4 along K)
    constexpr int AK4   = BK / 4;
    constexpr int AROWS = NT / AK4;
    constexpr int APASS = BM / AROWS;
    const int aCol  = tid % AK4;
    const int aRow0 = tid / AK4;

    // B-tile loader (non-transposed, float4 along N)
    constexpr int BN4   = BN / 4;
    constexpr int BROWS = NT / BN4;
    constexpr int BPASS = BK / BROWS;
    const int bCol  = tid % BN4;
    const int bRow0 = tid / BN4;

    // B^T-tile loader (MODE 1, float4 along K)
    constexpr int TBROWS = NT / AK4;
    constexpr int TBPASS = BN / TBROWS;
    const int tbK  = tid % AK4;
    const int tbN0 = tid / AK4;

    for (int k0 = 0; k0 < kend; k0 += BK) {
        __syncthreads();

        // ---- load A tile (transposed store As[k][m]) ----
        #pragma unroll
        for (int p = 0; p < APASS; p++) {
            const int r = aRow0 + p * AROWS;
            const float4 av = *reinterpret_cast<const float4*>(
                &A[aoff + (size_t)(by * BM + r) * lda + k0 + aCol * 4]);
            float vv[4] = {av.x, av.y, av.z, av.w};
            if (MODE == 2) {
                const int   i_glob = by * BM + r;
                const float mi = sm_m[r];
                const float il = sm_il[r];
                #pragma unroll
                for (int u = 0; u < 4; u++) {
                    const int j = k0 + aCol * 4 + u;
                    vv[u] = (j <= i_glob) ? __expf(vv[u] - mi) * il : 0.f;
                }
            }
            #pragma unroll
            for (int u = 0; u < 4; u++) As[aCol * 4 + u][r] = vv[u];
        }

        // ---- load B tile ----
        if (MODE == 1) {
            #pragma unroll
            for (int p = 0; p < TBPASS; p++) {
                const int n = tbN0 + p * TBROWS;
                const float4 bv = *reinterpret_cast<const float4*>(
                    &Bm[boff + (size_t)(bx * BN + n) * ldb + k0 + tbK * 4]);
                Bs[tbK * 4 + 0][n] = bv.x;
                Bs[tbK * 4 + 1][n] = bv.y;
                Bs[tbK * 4 + 2][n] = bv.z;
                Bs[tbK * 4 + 3][n] = bv.w;
            }
        } else {
            #pragma unroll
            for (int p = 0; p < BPASS; p++) {
                const int r = bRow0 + p * BROWS;
                const float4 bv = *reinterpret_cast<const float4*>(
                    &Bm[boff + (size_t)(k0 + r) * ldb + bx * BN + bCol * 4]);
                *reinterpret_cast<float4*>(&Bs[r][bCol * 4]) = bv;
            }
        }
        __syncthreads();

        // ---- compute ----
        #pragma unroll
        for (int kk = 0; kk < BK; ++kk) {
            float ra[TM], rb[TN];
            #pragma unroll
            for (int m = 0; m < TM; m += 4)
                *reinterpret_cast<float4*>(&ra[m]) =
                    *reinterpret_cast<const float4*>(&As[kk][trow * TM + m]);
            #pragma unroll
            for (int n = 0; n < TN; n += 4)
                *reinterpret_cast<float4*>(&rb[n]) =
                    *reinterpret_cast<const float4*>(&Bs[kk][tcol * TN + n]);
            #pragma unroll
            for (int m = 0; m < TM; m++)
                #pragma unroll
                for (int n = 0; n < TN; n++)
                    acc[m][n] += ra[m] * rb[n];
        }
    }

    // ---- epilogue (vectorized stores) ----
    #pragma unroll
    for (int m = 0; m < TM; m++) {
        const int gr = by * BM + trow * TM + m;
        const size_t base = coff + (size_t)gr * ldc + bx * BN + tcol * TN;
        #pragma unroll
        for (int n0 = 0; n0 < TN; n0 += 4) {
            float4 o;
            o.x = acc[m][n0 + 0] * alpha;
            o.y = acc[m][n0 + 1] * alpha;
            o.z = acc[m][n0 + 2] * alpha;
            o.w = acc[m][n0 + 3] * alpha;
            if (MODE == 0 && bias != nullptr) {
                const float4 bb = *reinterpret_cast<const float4*>(
                    &bias[bx * BN + tcol * TN + n0]);
                o.x += bb.x; o.y += bb.y; o.z += bb.z; o.w += bb.w;
            }
            *reinterpret_cast<float4*>(&C[base + n0]) = o;
        }
    }
}

// ---------------------------------------------------------------------------
// Per-row causal softmax stats: m = max_{j<=i} raw, l = sum exp(raw - m)
// one block (256 threads) per row
// ---------------------------------------------------------------------------
__global__ __launch_bounds__(256)
void softmax_stats_kernel(const float* __restrict__ raw,
                          float* __restrict__ gm, float* __restrict__ gl)
{
    const int i = blockIdx.x;     // row within (h,b)
    const int z = blockIdx.y;     // h*B + b
    const float* row = raw + ((size_t)z * S_ + i) * (size_t)S_;
    const int tid = threadIdx.x;

    float v[16];
    #pragma unroll
    for (int t = 0; t < 4; t++) {
        const int j4 = t * 256 + tid;
        const float4 x = *reinterpret_cast<const float4*>(&row[j4 * 4]);
        const int j0 = j4 * 4;
        v[t * 4 + 0] = (j0 + 0 <= i) ? x.x : -CUDART_INF_F;
        v[t * 4 + 1] = (j0 + 1 <= i) ? x.y : -CUDART_INF_F;
        v[t * 4 + 2] = (j0 + 2 <= i) ? x.z : -CUDART_INF_F;
        v[t * 4 + 3] = (j0 + 3 <= i) ? x.w : -CUDART_INF_F;
    }

    float lm = v[0];
    #pragma unroll
    for (int t = 1; t < 16; t++) lm = fmaxf(lm, v[t]);

    __shared__ float red[256];
    red[tid] = lm;
    __syncthreads();
    #pragma unroll
    for (int s = 128; s > 0; s >>= 1) {
        if (tid < s) red[tid] = fmaxf(red[tid], red[tid + s]);
        __syncthreads();
    }
    const float m = red[0];
    __syncthreads();

    float ls = 0.f;
    #pragma unroll
    for (int t = 0; t < 16; t++) ls += __expf(v[t] - m);  // exp(-inf)=0
    red[tid] = ls;
    __syncthreads();
    #pragma unroll
    for (int s = 128; s > 0; s >>= 1) {
        if (tid < s) red[tid] += red[tid + s];
        __syncthreads();
    }
    if (tid == 0) {
        gm[(size_t)z * S_ + i] = m;
        gl[(size_t)z * S_ + i] = red[0];
    }
}

// ---------------------------------------------------------------------------
extern "C" void kernel_launch(void* const* d_in, const int* in_sizes, int n_in,
                              void* d_out, int out_size)
{
    const float* x  = (const float*)d_in[0];
    const float* Wq = (const float*)d_in[1];
    const float* bq = (const float*)d_in[2];
    const float* Wk = (const float*)d_in[3];
    const float* bk = (const float*)d_in[4];
    const float* Wv = (const float*)d_in[5];
    const float* bv = (const float*)d_in[6];
    const float* Wo = (const float*)d_in[7];
    const float* bo = (const float*)d_in[8];

    float* sa  = (float*)d_out;                 // [B,S,512]
    float* raw = (float*)d_out + SA_ELEMS;      // [16,4096,4096]

    float *qp, *kp, *vp, *cp, *mp, *lp;
    cudaGetSymbolAddress((void**)&qp, g_q);
    cudaGetSymbolAddress((void**)&kp, g_k);
    cudaGetSymbolAddress((void**)&vp, g_v);
    cudaGetSymbolAddress((void**)&cp, g_ctx);
    cudaGetSymbolAddress((void**)&mp, g_m);
    cudaGetSymbolAddress((void**)&lp, g_l);

    const dim3 blk(256);

    // 1-3) QKV projections: [8192,512] @ [512,512] + bias
    const dim3 gproj(D_ / 128, MR / 128, 1);
    gemm_kernel<0,128,128,16,8,8><<<gproj, blk>>>(x, D_, Wq, D_, bq, qp, D_,
                                                  MR, D_, D_, 1.f, nullptr, nullptr);
    gemm_kernel<0,128,128,16,8,8><<<gproj, blk>>>(x, D_, Wk, D_, bk, kp, D_,
                                                  MR, D_, D_, 1.f, nullptr, nullptr);
    gemm_kernel<0,128,128,16,8,8><<<gproj, blk>>>(x, D_, Wv, D_, bv, vp, D_,
                                                  MR, D_, D_, 1.f, nullptr, nullptr);

    // 4) scores: raw[z] = Q_z @ K_z^T / 8   (full S x S, pre-mask)
    const dim3 gsc(S_ / 128, S_ / 128, H_ * B_);
    gemm_kernel<1,128,128,16,8,8><<<gsc, blk>>>(qp, D_, kp, D_, nullptr, raw, S_,
                                                S_, S_, DH, 0.125f, nullptr, nullptr);

    // 5) per-row causal softmax stats
    softmax_stats_kernel<<<dim3(S_, H_ * B_), blk>>>(raw, mp, lp);

    // 6) PV: ctx = softmax(raw) @ V   (causal k-range)
    const dim3 gpv(DH / 64, S_ / 128, H_ * B_);
    gemm_kernel<2,128,64,16,8,4><<<gpv, blk>>>(raw, S_, vp, D_, nullptr, cp, D_,
                                               S_, DH, S_, 1.f, mp, lp);

    // 7) output projection: sa = ctx @ Wo + bo
    gemm_kernel<0,128,128,16,8,8><<<gproj, blk>>>(cp, D_, Wo, D_, bo, sa, D_,
                                                  MR, D_, D_, 1.f, nullptr, nullptr);
}